// round 2
// baseline (speedup 1.0000x reference)
#include <cuda_runtime.h>
#include <math.h>

// TransformationRotationLoss — single fused streaming reduction.
// loss[j] = mean_over_masked_rows( ALPHA*u_ta[j]^2 + BETTA*u_tb[j]^2 )
// sin(arccos c) = sqrt(1-c^2), cos(arccos c)-1 = c-1.

#define ALPHA 0.7f
#define BETTA 0.3f

static constexpr int THREADS    = 256;
static constexpr int MAX_BLOCKS = 1024;

__device__ float4 g_partials[MAX_BLOCKS];
__device__ unsigned int g_ticket = 0;

__device__ __forceinline__ void process_row(
    float ax, float ay, float az,
    float bx, float by, float bz,
    float& sx, float& sy, float& sz, float& cnt)
{
    float r1sq = fmaf(ax, ax, fmaf(ay, ay, az * az));
    if (!(r1sq > 1e-16f)) return;   // mask: ||v1|| > 1e-8
    float r2sq = fmaf(bx, bx, fmaf(by, by, bz * bz));

    float inv1 = rsqrtf(r1sq);
    float inv2 = (r2sq > 0.0f) ? rsqrtf(r2sq) : 1.0f;

    float n1x = ax * inv1, n1y = ay * inv1, n1z = az * inv1;
    float u2x = bx * inv2, u2y = by * inv2, u2z = bz * inv2;

    float c = fmaf(n1x, u2x, fmaf(n1y, u2y, n1z * u2z));
    c = fminf(1.0f, fmaxf(-1.0f, c));

    // Gram-Schmidt: p = v2 - n1*(n1·v2), n2 = unit(p)
    float proj = fmaf(n1x, bx, fmaf(n1y, by, n1z * bz));
    float px = fmaf(-n1x, proj, bx);
    float py = fmaf(-n1y, proj, by);
    float pz = fmaf(-n1z, proj, bz);
    float psq = fmaf(px, px, fmaf(py, py, pz * pz));
    float invp = (psq > 0.0f) ? rsqrtf(psq) : 1.0f;
    float n2x = px * invp, n2y = py * invp, n2z = pz * invp;

    float sina = sqrtf(fmaxf(1.0f - c * c, 0.0f));
    float cm1  = c - 1.0f;

    float s1 = n1x + n1y + n1z;
    float s2 = n2x + n2y + n2z;

    float tax = sina * fmaf(n2x, s1, -n1x * s2);
    float tay = sina * fmaf(n2y, s1, -n1y * s2);
    float taz = sina * fmaf(n2z, s1, -n1z * s2);

    float tbx = cm1 * fmaf(n1x, s1, n2x * s2);
    float tby = cm1 * fmaf(n1y, s1, n2y * s2);
    float tbz = cm1 * fmaf(n1z, s1, n2z * s2);

    sx += fmaf(ALPHA, tax * tax, BETTA * tbx * tbx);
    sy += fmaf(ALPHA, tay * tay, BETTA * tby * tby);
    sz += fmaf(ALPHA, taz * taz, BETTA * tbz * tbz);
    cnt += 1.0f;
}

__device__ __forceinline__ void process_group(
    const float4& a0, const float4& a1, const float4& a2,
    const float4& b0, const float4& b1, const float4& b2,
    float& sx, float& sy, float& sz, float& cnt)
{
    process_row(a0.x, a0.y, a0.z, b0.x, b0.y, b0.z, sx, sy, sz, cnt);
    process_row(a0.w, a1.x, a1.y, b0.w, b1.x, b1.y, sx, sy, sz, cnt);
    process_row(a1.z, a1.w, a2.x, b1.z, b1.w, b2.x, sx, sy, sz, cnt);
    process_row(a2.y, a2.z, a2.w, b2.y, b2.z, b2.w, sx, sy, sz, cnt);
}

// Block-reduce (sx,sy,sz,cnt) into shared `result`; valid after __syncthreads.
__device__ __forceinline__ void block_reduce(
    float sx, float sy, float sz, float cnt, float4* result)
{
    #pragma unroll
    for (int o = 16; o > 0; o >>= 1) {
        sx  += __shfl_down_sync(0xffffffffu, sx,  o);
        sy  += __shfl_down_sync(0xffffffffu, sy,  o);
        sz  += __shfl_down_sync(0xffffffffu, sz,  o);
        cnt += __shfl_down_sync(0xffffffffu, cnt, o);
    }
    __shared__ float4 smem[THREADS / 32];
    int lane = threadIdx.x & 31;
    int warp = threadIdx.x >> 5;
    if (lane == 0) smem[warp] = make_float4(sx, sy, sz, cnt);
    __syncthreads();
    if (warp == 0) {
        float4 v = (lane < (blockDim.x >> 5)) ? smem[lane]
                                              : make_float4(0.f, 0.f, 0.f, 0.f);
        sx = v.x; sy = v.y; sz = v.z; cnt = v.w;
        #pragma unroll
        for (int o = 16; o > 0; o >>= 1) {
            sx  += __shfl_down_sync(0xffffffffu, sx,  o);
            sy  += __shfl_down_sync(0xffffffffu, sy,  o);
            sz  += __shfl_down_sync(0xffffffffu, sz,  o);
            cnt += __shfl_down_sync(0xffffffffu, cnt, o);
        }
        if (lane == 0) *result = make_float4(sx, sy, sz, cnt);
    }
    __syncthreads();
}

__device__ __forceinline__ float fix_num(float x) {
    if (isnan(x)) return 0.0f;
    if (isinf(x)) return x > 0.0f ? 0.1f : -0.1f;
    return x;
}

__global__ __launch_bounds__(THREADS)
void trl_fused_kernel(const float* __restrict__ v1,
                      const float* __restrict__ v2,
                      float* __restrict__ out,
                      int rows)
{
    float sx = 0.f, sy = 0.f, sz = 0.f, cnt = 0.f;

    const int tid    = blockIdx.x * blockDim.x + threadIdx.x;
    const int stride = gridDim.x * blockDim.x;
    const int rows4  = rows >> 2;      // groups of 4 rows = 3 float4 per input

    const float4* __restrict__ a4 = reinterpret_cast<const float4*>(v1);
    const float4* __restrict__ b4 = reinterpret_cast<const float4*>(v2);

    // Two front-batched groups per thread (12 independent LDG.128 in flight).
    int g0 = tid;
    int g1 = tid + stride;
    if (g1 < rows4) {
        float4 a00 = a4[3 * g0 + 0], a01 = a4[3 * g0 + 1], a02 = a4[3 * g0 + 2];
        float4 a10 = a4[3 * g1 + 0], a11 = a4[3 * g1 + 1], a12 = a4[3 * g1 + 2];
        float4 b00 = b4[3 * g0 + 0], b01 = b4[3 * g0 + 1], b02 = b4[3 * g0 + 2];
        float4 b10 = b4[3 * g1 + 0], b11 = b4[3 * g1 + 1], b12 = b4[3 * g1 + 2];
        process_group(a00, a01, a02, b00, b01, b02, sx, sy, sz, cnt);
        process_group(a10, a11, a12, b10, b11, b12, sx, sy, sz, cnt);
    } else if (g0 < rows4) {
        float4 a00 = a4[3 * g0 + 0], a01 = a4[3 * g0 + 1], a02 = a4[3 * g0 + 2];
        float4 b00 = b4[3 * g0 + 0], b01 = b4[3 * g0 + 1], b02 = b4[3 * g0 + 2];
        process_group(a00, a01, a02, b00, b01, b02, sx, sy, sz, cnt);
    }
    // Remainder groups (only if rows4 > 2*stride)
    for (int g = tid + 2 * stride; g < rows4; g += stride) {
        float4 a0 = a4[3 * g + 0], a1 = a4[3 * g + 1], a2 = a4[3 * g + 2];
        float4 b0 = b4[3 * g + 0], b1 = b4[3 * g + 1], b2 = b4[3 * g + 2];
        process_group(a0, a1, a2, b0, b1, b2, sx, sy, sz, cnt);
    }
    // Tail rows (rows % 4)
    for (int r = (rows4 << 2) + tid; r < rows; r += stride) {
        process_row(v1[3 * r], v1[3 * r + 1], v1[3 * r + 2],
                    v2[3 * r], v2[3 * r + 1], v2[3 * r + 2],
                    sx, sy, sz, cnt);
    }

    __shared__ float4 result;
    block_reduce(sx, sy, sz, cnt, &result);

    // Publish this block's partial; last block to arrive finalizes.
    __shared__ bool is_last;
    if (threadIdx.x == 0) {
        g_partials[blockIdx.x] = result;
        __threadfence();
        unsigned int t = atomicAdd(&g_ticket, 1u);
        is_last = (t == gridDim.x - 1);
    }
    __syncthreads();

    if (is_last) {
        float fx = 0.f, fy = 0.f, fz = 0.f, fc = 0.f;
        for (int i = threadIdx.x; i < (int)gridDim.x; i += blockDim.x) {
            float4 p;
            const float4* src = &g_partials[i];
            // L2-coherent load (skip L1)
            asm volatile("ld.global.cg.v4.f32 {%0,%1,%2,%3}, [%4];"
                         : "=f"(p.x), "=f"(p.y), "=f"(p.z), "=f"(p.w)
                         : "l"(src));
            fx += p.x; fy += p.y; fz += p.z; fc += p.w;
        }
        __shared__ float4 final_r;
        block_reduce(fx, fy, fz, fc, &final_r);
        if (threadIdx.x == 0) {
            float inv = 1.0f / fmaxf(final_r.w, 1.0f);
            out[0] = fix_num(final_r.x * inv);
            out[1] = fix_num(final_r.y * inv);
            out[2] = fix_num(final_r.z * inv);
            g_ticket = 0;   // reset for next (graph-replayed) launch
        }
    }
}

extern "C" void kernel_launch(void* const* d_in, const int* in_sizes, int n_in,
                              void* d_out, int out_size)
{
    const float* v1 = (const float*)d_in[0];
    const float* v2 = (const float*)d_in[1];
    float* out = (float*)d_out;

    int rows  = in_sizes[0] / 3;
    int rows4 = rows >> 2;
    // Target ~2 groups per thread.
    int blocks = (rows4 / 2 + THREADS - 1) / THREADS;
    if (blocks < 1) blocks = 1;
    if (blocks > MAX_BLOCKS) blocks = MAX_BLOCKS;

    trl_fused_kernel<<<blocks, THREADS>>>(v1, v2, out, rows);
}